// round 8
// baseline (speedup 1.0000x reference)
#include <cuda_runtime.h>
#include <cuda_bf16.h>
#include <math.h>
#include <cstdint>

#define BATCH 1024
#define L 32
#define D 128
#define NNODE 50000
#define ROWS (BATCH * L)           // 32768
#define RD   (ROWS * D)            // 4194304
#define BD   (BATCH * D)           // 131072
#define ED   (NNODE * D)           // 6400000

// ---------------- float scratch ----------------
#define F_HG   0L                   // [ROWS, 640] = hin|hout|gh(384); later reused [ROWS,384] for gh2
#define F_GI   (5L * RD)            // [ROWS, 384]
#define F_FW2  (8L * RD)
#define F_FIN  (9L * RD)
#define F_TOTAL (10L * RD)
__device__ float g_f[F_TOTAL];
__device__ float g_bio[640];        // concat(b_in, b_out, zeros[384])

// ---------------- bf16 split planes ----------------
#define BO_GAH  0L
#define BO_GAL  ((long)RD)
#define BO_AH   (2L * RD)
#define BO_AL   (4L * RD)
#define BO_ITH  (6L * RD)
#define BO_ITL  (7L * RD)
#define BO_FNH  (8L * RD)
#define BO_FNL  (9L * RD)
#define BO_IEH  (10L * RD)
#define BO_IEL  (11L * RD)
#define BO_HSH  (12L * RD)
#define BO_HSL  (12L * RD + BD)
#define BO_EBH  (12L * RD + 2L * BD)
#define BO_EBL  (12L * RD + 2L * BD + ED)
#define BO_WZ   (12L * RD + 2L * BD + 2L * ED)
// merged [Wio(256) | U_h(384)] -> [640,128]: hi plane 81920, lo plane 81920
#define OW_WIOU (BO_WZ)
#define OW_WA   (OW_WIOU + 163840L)  // [384,256]
#define OW_WI   (OW_WA + 196608L)    // [384,128]
#define OW_WH   (OW_WI + 98304L)
#define OW_W2   (OW_WH + 98304L)     // [128,128]
#define B_TOTAL (OW_W2 + 32768L)
__device__ __nv_bfloat16 g_bf[B_TOTAL];

// ---------------- helpers ----------------
__device__ __forceinline__ uint32_t smem_u32(const void* p) {
    uint32_t a;
    asm("{ .reg .u64 t; cvta.to.shared.u64 t, %1; cvt.u32.u64 %0, t; }" : "=r"(a) : "l"(p));
    return a;
}
__device__ __forceinline__ void wsplit(float v, __nv_bfloat16* hp, __nv_bfloat16* lp, long i) {
    __nv_bfloat16 h = __float2bfloat16(v);
    hp[i] = h;
    lp[i] = __float2bfloat16(v - __bfloat162float(h));
}
__device__ __forceinline__ float sigf(float x) { return 1.0f / (1.0f + expf(-x)); }

__device__ __forceinline__ void mma_bf16(float* d, const uint32_t* a, const uint32_t* b) {
    asm volatile(
        "mma.sync.aligned.m16n8k16.row.col.f32.bf16.bf16.f32 "
        "{%0,%1,%2,%3}, {%4,%5,%6,%7}, {%8,%9}, {%0,%1,%2,%3};"
        : "+f"(d[0]), "+f"(d[1]), "+f"(d[2]), "+f"(d[3])
        : "r"(a[0]), "r"(a[1]), "r"(a[2]), "r"(a[3]), "r"(b[0]), "r"(b[1]));
}
__device__ __forceinline__ void ldsm4(uint32_t* r, uint32_t a) {
    asm volatile("ldmatrix.sync.aligned.m8n8.x4.shared.b16 {%0,%1,%2,%3}, [%4];"
        : "=r"(r[0]), "=r"(r[1]), "=r"(r[2]), "=r"(r[3]) : "r"(a));
}

// ================= split-bf16 tensor-core GEMM =================
// C[M,N] = (Ah+Al)[M,K] @ (Bh+Bl)[N,K]^T (+bias), fp32 accum.
// Block 128x128, 8 warps (2m x 4n), warp tile 64x32, K-chunk 32.
// 2-stage cp.async pipeline, ONE __syncthreads per chunk.
#define BM 128
#define BN 128
#define BK 32
#define PLANE (128 * 40)
#define PLANEB (PLANE * 2)
#define STAGEB (4 * PLANEB)
#define GEMM_SMEM (2 * STAGEB)      // 81920

__global__ void __launch_bounds__(256) gemm_mma(
    long ah, long al, long bh, long bl,
    const float* __restrict__ bias_ext, int bias_mode,
    float* __restrict__ C_ext, long c_off, int N, int K)
{
    extern __shared__ __align__(16) __nv_bfloat16 dsm[];
    const __nv_bfloat16* Ah = g_bf + ah;
    const __nv_bfloat16* Al = g_bf + al;
    const __nv_bfloat16* Bh = g_bf + bh;
    const __nv_bfloat16* Bl = g_bf + bl;
    float* C = C_ext ? C_ext : (g_f + c_off);
    const float* bias = (bias_mode == 1) ? bias_ext : (bias_mode == 2 ? g_bio : nullptr);

    const int tid = threadIdx.x;
    const int warp = tid >> 5, lane = tid & 31;
    const int wm = warp & 1, wn = warp >> 1;
    const int g = lane >> 2, tig = lane & 3;

    const long bm = (long)blockIdx.x * BM;
    const int bn = blockIdx.y * BN;
    const int nsize = min(BN, N - bn);

    const int fr = tid >> 1;
    const int fc = (tid & 1) * 16;
    const long arow = bm + fr;
    const long brow = bn + (fr < nsize ? fr : 0);
    const int bok = (fr < nsize) ? 16 : 0;
    const uint32_t smb = smem_u32(dsm);
    const uint32_t doff = (uint32_t)(fr * 80 + fc * 2);

    const uint32_t laneA = (uint32_t)(((lane & 7) + (((lane >> 3) & 1) << 3)) * 80 + (lane >> 4) * 16);
    const uint32_t laneB = (uint32_t)(((lane & 7) + ((lane >> 4) << 3)) * 80 + ((lane >> 3) & 1) * 16);
    const uint32_t aBaseA = (uint32_t)(wm * 64 * 80) + laneA;
    const uint32_t aBaseB = (uint32_t)(wn * 32 * 80) + laneB;

    float acc[4][4][4];
#pragma unroll
    for (int i = 0; i < 4; i++)
#pragma unroll
        for (int j = 0; j < 4; j++)
#pragma unroll
            for (int v = 0; v < 4; v++) acc[i][j][v] = 0.f;

#define LOADCH(c_, st_) do {                                                           \
    const long k0_ = (long)(c_) * BK;                                                  \
    const uint32_t b_ = smb + (uint32_t)(st_) * STAGEB;                                \
    const __nv_bfloat16* pa_ = Ah + arow * K + k0_ + fc;                               \
    const __nv_bfloat16* qa_ = Al + arow * K + k0_ + fc;                               \
    const __nv_bfloat16* pb_ = Bh + brow * K + k0_ + fc;                               \
    const __nv_bfloat16* qb_ = Bl + brow * K + k0_ + fc;                               \
    asm volatile("cp.async.cg.shared.global [%0], [%1], 16;" :: "r"(b_ + doff), "l"(pa_)); \
    asm volatile("cp.async.cg.shared.global [%0], [%1], 16;" :: "r"(b_ + doff + 16), "l"(pa_ + 8)); \
    asm volatile("cp.async.cg.shared.global [%0], [%1], 16;" :: "r"(b_ + PLANEB + doff), "l"(qa_)); \
    asm volatile("cp.async.cg.shared.global [%0], [%1], 16;" :: "r"(b_ + PLANEB + doff + 16), "l"(qa_ + 8)); \
    asm volatile("cp.async.cg.shared.global [%0], [%1], 16, %2;" :: "r"(b_ + 2 * PLANEB + doff), "l"(pb_), "r"(bok)); \
    asm volatile("cp.async.cg.shared.global [%0], [%1], 16, %2;" :: "r"(b_ + 2 * PLANEB + doff + 16), "l"(pb_ + 8), "r"(bok)); \
    asm volatile("cp.async.cg.shared.global [%0], [%1], 16, %2;" :: "r"(b_ + 3 * PLANEB + doff), "l"(qb_), "r"(bok)); \
    asm volatile("cp.async.cg.shared.global [%0], [%1], 16, %2;" :: "r"(b_ + 3 * PLANEB + doff + 16), "l"(qb_ + 8), "r"(bok)); \
    asm volatile("cp.async.commit_group;");                                            \
} while (0)

    const int nch = K / BK;
    LOADCH(0, 0);
    for (int c = 0; c < nch; c++) {
        const int st = c & 1;
        asm volatile("cp.async.wait_group 0;");
        __syncthreads();
        // issue next chunk AFTER the barrier: all warps have finished reading
        // the stage being overwritten (last read at iter c-1). Copies overlap compute.
        if (c + 1 < nch) LOADCH(c + 1, st ^ 1);

        const uint32_t stb = smb + (uint32_t)st * STAGEB;
        const uint32_t pAh = stb + aBaseA;
        const uint32_t pAl = stb + PLANEB + aBaseA;
        const uint32_t pBh = stb + 2 * PLANEB + aBaseB;
        const uint32_t pBl = stb + 3 * PLANEB + aBaseB;

#pragma unroll
        for (int ks = 0; ks < 2; ks++) {
            const uint32_t ko = (uint32_t)(ks * 32);
            uint32_t ahf[4][4], alf[4][4], bhf[4][2], blf[4][2];
#pragma unroll
            for (int mf = 0; mf < 4; mf++) {
                ldsm4(ahf[mf], pAh + (uint32_t)(mf * 16 * 80) + ko);
                ldsm4(alf[mf], pAl + (uint32_t)(mf * 16 * 80) + ko);
            }
#pragma unroll
            for (int np = 0; np < 2; np++) {
                uint32_t bt[4];
                ldsm4(bt, pBh + (uint32_t)(np * 16 * 80) + ko);
                bhf[np * 2][0] = bt[0]; bhf[np * 2][1] = bt[1];
                bhf[np * 2 + 1][0] = bt[2]; bhf[np * 2 + 1][1] = bt[3];
                ldsm4(bt, pBl + (uint32_t)(np * 16 * 80) + ko);
                blf[np * 2][0] = bt[0]; blf[np * 2][1] = bt[1];
                blf[np * 2 + 1][0] = bt[2]; blf[np * 2 + 1][1] = bt[3];
            }
#pragma unroll
            for (int mf = 0; mf < 4; mf++)
#pragma unroll
                for (int nf = 0; nf < 4; nf++) {
                    mma_bf16(acc[mf][nf], ahf[mf], bhf[nf]);
                    mma_bf16(acc[mf][nf], ahf[mf], blf[nf]);
                    mma_bf16(acc[mf][nf], alf[mf], bhf[nf]);
                }
        }
    }

#pragma unroll
    for (int mf = 0; mf < 4; mf++) {
        const long row = bm + wm * 64 + mf * 16 + g;
#pragma unroll
        for (int nf = 0; nf < 4; nf++) {
            const int col = bn + wn * 32 + nf * 8 + tig * 2;
            if (col < N) {
                float bx = bias ? bias[col] : 0.f;
                float by = bias ? bias[col + 1] : 0.f;
                *(float2*)&C[row * N + col] =
                    make_float2(acc[mf][nf][0] + bx, acc[mf][nf][1] + by);
                *(float2*)&C[(row + 8) * N + col] =
                    make_float2(acc[mf][nf][2] + bx, acc[mf][nf][3] + by);
            }
        }
    }
#undef LOADCH
}

// ================= fused prep =================
// ranges: Wio 32768 | Uh 49152 | bio 640 | Wa 98304 | Wi 49152 | Wh 49152 |
//         W2 16384 | emb ED | inter RD | gather RD
#define PREP_TOTAL (32768L + 49152 + 640 + 98304 + 49152 + 49152 + 16384 + (long)ED + 2L * RD)
__global__ void __launch_bounds__(256) prep_all(
    const float* __restrict__ W_in, const float* __restrict__ b_in,
    const float* __restrict__ W_out, const float* __restrict__ b_out,
    const float* __restrict__ W_a, const float* __restrict__ U_h,
    const float* __restrict__ Wi, const float* __restrict__ Wh,
    const float* __restrict__ W2,
    const float* __restrict__ emb, const float* __restrict__ inter,
    const int* __restrict__ items)
{
    long i = (long)blockIdx.x * 256 + threadIdx.x;
    if (i < 32768) {                                    // Wio part of merged [640,128]
        int n = (int)(i >> 7), k = (int)(i & 127);
        float v = (n < 128) ? W_in[k * 128 + n] : W_out[k * 128 + (n - 128)];
        wsplit(v, g_bf + OW_WIOU, g_bf + OW_WIOU + 81920, i);
        return;
    }
    i -= 32768;
    if (i < 49152) {                                    // U_h part: rows 256..639
        int n = (int)(i >> 7), k = (int)(i & 127);
        wsplit(U_h[(long)k * 384 + n], g_bf + OW_WIOU + 32768, g_bf + OW_WIOU + 81920 + 32768, i);
        return;
    }
    i -= 49152;
    if (i < 640) {
        g_bio[i] = (i < 128) ? b_in[i] : (i < 256 ? b_out[i - 128] : 0.f);
        return;
    }
    i -= 640;
    if (i < 98304) {                                    // W_a [384,256]
        int n = (int)(i >> 8), k = (int)(i & 255);
        wsplit(W_a[(long)k * 384 + n], g_bf + OW_WA, g_bf + OW_WA + 98304, i);
        return;
    }
    i -= 98304;
    if (i < 49152) {                                    // Wi [384,128]
        int n = (int)(i >> 7), k = (int)(i & 127);
        wsplit(Wi[(long)k * 384 + n], g_bf + OW_WI, g_bf + OW_WI + 49152, i);
        return;
    }
    i -= 49152;
    if (i < 49152) {                                    // Wh [384,128]
        int n = (int)(i >> 7), k = (int)(i & 127);
        wsplit(Wh[(long)k * 384 + n], g_bf + OW_WH, g_bf + OW_WH + 49152, i);
        return;
    }
    i -= 49152;
    if (i < 16384) {                                    // W2 [128,128]
        int n = (int)(i >> 7), k = (int)(i & 127);
        wsplit(W2[(long)k * 128 + n], g_bf + OW_W2, g_bf + OW_W2 + 16384, i);
        return;
    }
    i -= 16384;
    if (i < (long)ED) {
        wsplit(emb[i], g_bf + BO_EBH, g_bf + BO_EBH + (long)ED, i);
        return;
    }
    i -= (long)ED;
    if (i < (long)RD) {
        wsplit(inter[i], g_bf + BO_IEH, g_bf + BO_IEH + (long)RD, i);
        return;
    }
    i -= (long)RD;
    if (i < (long)RD) {
        int row = (int)(i >> 7), d = (int)(i & 127);
        wsplit(emb[(long)items[row] * D + d], g_bf + BO_GAH, g_bf + BO_GAL, i);
    }
}

// ================= adjacency (hio from [ROWS,640] cols 0..255) =================
__global__ void __launch_bounds__(128) adj_kernel(const float* __restrict__ Ain, const float* __restrict__ Aout) {
    const float* hg = g_f + F_HG;
    const int b = blockIdx.x, d = threadIdx.x;
    __shared__ float sAi[L * L], sAo[L * L], shi[L * D], sho[L * D];
    const float* Aib = Ain + (long)b * L * L;
    const float* Aob = Aout + (long)b * L * L;
    for (int i = d; i < L * L; i += 128) { sAi[i] = Aib[i]; sAo[i] = Aob[i]; }
    for (int i = d; i < L * D; i += 128) {
        int m = i >> 7, dd = i & 127;
        long r = ((long)b * L + m) * 640;
        shi[i] = hg[r + dd];
        sho[i] = hg[r + 128 + dd];
    }
    __syncthreads();
    for (int l = 0; l < L; l++) {
        float si = 0.f, so = 0.f;
#pragma unroll 8
        for (int m = 0; m < L; m++) {
            si += sAi[l * L + m] * shi[m * D + d];
            so += sAo[l * L + m] * sho[m * D + d];
        }
        long o = ((long)b * L + l) * 256;
        wsplit(si, g_bf + BO_AH, g_bf + BO_AL, o + d);
        wsplit(so, g_bf + BO_AH, g_bf + BO_AL, o + 128 + d);
    }
}

// ================= GRU kernels =================
// GRU1: gi [ROWS,384] @ F_GI; gh = cols 256..639 of [ROWS,640] @ F_HG
__global__ void __launch_bounds__(256) gru1_kernel(const int* __restrict__ items, const float* __restrict__ emb) {
    long i = (long)blockIdx.x * 256 + threadIdx.x;
    if (i >= (long)RD) return;
    int row = (int)(i >> 7), d = (int)(i & 127);
    const float* gi = g_f + F_GI + (long)row * 384;
    const float* gh = g_f + F_HG + (long)row * 640 + 256;
    float r = sigf(gi[d] + gh[d]);
    float z = sigf(gi[128 + d] + gh[128 + d]);
    float n = tanhf(gi[256 + d] + r * gh[256 + d]);
    float hp = emb[(long)items[row] * D + d];
    wsplit((1.f - z) * n + z * hp, g_bf + BO_ITH, g_bf + BO_ITL, i);
}

// GRU2: gi [ROWS,384] @ F_GI; gh [ROWS,384] @ F_HG
__global__ void __launch_bounds__(256) gru2_kernel(const float* __restrict__ inter) {
    long i = (long)blockIdx.x * 256 + threadIdx.x;
    if (i >= (long)RD) return;
    int row = (int)(i >> 7), d = (int)(i & 127);
    const float* gi = g_f + F_GI + (long)row * 384;
    const float* gh = g_f + F_HG + (long)row * 384;
    float r = sigf(gi[d] + gh[d]);
    float z = sigf(gi[128 + d] + gh[128 + d]);
    float n = tanhf(gi[256 + d] + r * gh[256 + d]);
    float v = (1.f - z) * n + z * inter[i];
    g_f[F_FIN + i] = v;
    wsplit(v, g_bf + BO_FNH, g_bf + BO_FNL, i);
}

// ================= attention readout =================
__global__ void __launch_bounds__(128) readout_kernel(
    const int* __restrict__ seq_len,
    const float* __restrict__ W1, const float* __restrict__ b1,
    const float* __restrict__ wq, const float* __restrict__ bq,
    const float* __restrict__ W3, const float* __restrict__ b3)
{
    const float* fin = g_f + F_FIN;
    const float* fW2 = g_f + F_FW2;
    const int b = blockIdx.x, d = threadIdx.x;
    __shared__ float svn[D], sg_sh[D], gmat[L * D], alpha[L];

    const int sl = seq_len[b];
    const float* finb = fin + (long)b * L * D;
    svn[d] = finb[(long)(sl - 1) * D + d];
    __syncthreads();

    float q = b1[d];
    for (int k = 0; k < D; k++) q += svn[k] * W1[k * D + d];

    const float* fW2b = fW2 + (long)b * L * D;
    for (int l = 0; l < L; l++)
        gmat[l * D + d] = sigf(q + fW2b[l * D + d]);
    __syncthreads();

    int w = d >> 5, lane = d & 31;
    for (int l = w; l < L; l += 4) {
        float p = 0.f;
        for (int kk = lane; kk < D; kk += 32) p += gmat[l * D + kk] * wq[kk];
#pragma unroll
        for (int off = 16; off; off >>= 1) p += __shfl_xor_sync(0xFFFFFFFFu, p, off);
        if (lane == 0) alpha[l] = p + bq[0];
    }
    __syncthreads();

    float sg = 0.f;
    for (int l = 0; l < sl; l++) sg += alpha[l] * finb[(long)l * D + d];
    sg_sh[d] = sg;
    __syncthreads();

    float o = b3[d];
    for (int k = 0; k < D; k++) {
        o += svn[k]   * W3[k * D + d];
        o += sg_sh[k] * W3[(D + k) * D + d];
    }
    wsplit(o, g_bf + BO_HSH, g_bf + BO_HSL, (long)b * D + d);
}

// ================= launcher =================
extern "C" void kernel_launch(void* const* d_in, const int* in_sizes, int n_in,
                              void* d_out, int out_size)
{
    const int*   items  = (const int*)d_in[0];
    const float* A_in   = (const float*)d_in[1];
    const float* A_out  = (const float*)d_in[2];
    const float* inter  = (const float*)d_in[3];
    const int*   seqlen = (const int*)d_in[4];
    const float* emb    = (const float*)d_in[5];
    const float* W_in   = (const float*)d_in[6];
    const float* b_in   = (const float*)d_in[7];
    const float* W_out  = (const float*)d_in[8];
    const float* b_out  = (const float*)d_in[9];
    const float* W_a    = (const float*)d_in[10];
    const float* U_h    = (const float*)d_in[11];
    const float* b_gru  = (const float*)d_in[12];
    const float* Wi     = (const float*)d_in[13];
    const float* bi     = (const float*)d_in[14];
    const float* Wh     = (const float*)d_in[15];
    const float* bh     = (const float*)d_in[16];
    const float* W1     = (const float*)d_in[17];
    const float* b1     = (const float*)d_in[18];
    const float* W2     = (const float*)d_in[19];
    const float* b2     = (const float*)d_in[20];
    const float* wq     = (const float*)d_in[21];
    const float* bq     = (const float*)d_in[22];
    const float* W3     = (const float*)d_in[23];
    const float* b3     = (const float*)d_in[24];
    float* scores = (float*)d_out;

    cudaFuncSetAttribute(gemm_mma, cudaFuncAttributeMaxDynamicSharedMemorySize, GEMM_SMEM);

    const int MT = ROWS / 128;   // 256 M-tiles

    prep_all<<<(int)((PREP_TOTAL + 255) / 256), 256>>>(W_in, b_in, W_out, b_out, W_a, U_h,
                                                       Wi, Wh, W2, emb, inter, items);
    // [hio | gh] = gathered @ [W_in|W_out|U_h] + [bio|0]   (N=640, K=128)
    gemm_mma<<<dim3(MT, 5), 256, GEMM_SMEM>>>(BO_GAH, BO_GAL, OW_WIOU, OW_WIOU + 81920,
                                              nullptr, 2, nullptr, F_HG, 640, 128);
    adj_kernel<<<BATCH, 128>>>(A_in, A_out);
    gemm_mma<<<dim3(MT, 3), 256, GEMM_SMEM>>>(BO_AH, BO_AL, OW_WA, OW_WA + 98304,
                                              b_gru, 1, nullptr, F_GI, 384, 256);
    gru1_kernel<<<(RD + 255) / 256, 256>>>(items, emb);
    gemm_mma<<<dim3(MT, 3), 256, GEMM_SMEM>>>(BO_ITH, BO_ITL, OW_WI, OW_WI + 49152,
                                              bi, 1, nullptr, F_GI, 384, 128);
    gemm_mma<<<dim3(MT, 3), 256, GEMM_SMEM>>>(BO_IEH, BO_IEL, OW_WH, OW_WH + 49152,
                                              bh, 1, nullptr, F_HG, 384, 128);
    gru2_kernel<<<(RD + 255) / 256, 256>>>(inter);
    gemm_mma<<<dim3(MT, 1), 256, GEMM_SMEM>>>(BO_FNH, BO_FNL, OW_W2, OW_W2 + 16384,
                                              b2, 1, nullptr, F_FW2, 128, 128);
    readout_kernel<<<BATCH, 128>>>(seqlen, W1, b1, wq, bq, W3, b3);
    gemm_mma<<<dim3(BATCH / 128, (NNODE + 127) / 128), 256, GEMM_SMEM>>>(
        BO_HSH, BO_HSL, BO_EBH, BO_EBL, nullptr, 0, scores, 0, NNODE, 128);
}

// round 9
// speedup vs baseline: 1.1714x; 1.1714x over previous
#include <cuda_runtime.h>
#include <cuda_bf16.h>
#include <math.h>
#include <cstdint>

#define BATCH 1024
#define L 32
#define D 128
#define NNODE 50000
#define ROWS (BATCH * L)           // 32768
#define RD   (ROWS * D)            // 4194304
#define BD   (BATCH * D)           // 131072
#define ED   (NNODE * D)           // 6400000

// ---------------- float scratch ----------------
#define F_HG   0L                   // [ROWS, 640] = hin|hout|gh(384); later reused [ROWS,384] for gh2
#define F_GI   (5L * RD)            // [ROWS, 384]
#define F_FW2  (8L * RD)
#define F_FIN  (9L * RD)
#define F_TOTAL (10L * RD)
__device__ float g_f[F_TOTAL];
__device__ float g_bio[640];        // concat(b_in, b_out, zeros[384])

// ---------------- bf16 split planes ----------------
#define BO_GAH  0L
#define BO_GAL  ((long)RD)
#define BO_AH   (2L * RD)
#define BO_AL   (4L * RD)
#define BO_ITH  (6L * RD)
#define BO_ITL  (7L * RD)
#define BO_FNH  (8L * RD)
#define BO_FNL  (9L * RD)
#define BO_IEH  (10L * RD)
#define BO_IEL  (11L * RD)
#define BO_HSH  (12L * RD)
#define BO_HSL  (12L * RD + BD)
#define BO_EBH  (12L * RD + 2L * BD)
#define BO_EBL  (12L * RD + 2L * BD + ED)
#define BO_WZ   (12L * RD + 2L * BD + 2L * ED)
// merged [Wio(256) | U_h(384)] -> [640,128]: hi plane 81920, lo plane 81920
#define OW_WIOU (BO_WZ)
#define OW_WA   (OW_WIOU + 163840L)  // [384,256]
#define OW_WI   (OW_WA + 196608L)    // [384,128]
#define OW_WH   (OW_WI + 98304L)
#define OW_W2   (OW_WH + 98304L)     // [128,128]
#define B_TOTAL (OW_W2 + 32768L)
__device__ __nv_bfloat16 g_bf[B_TOTAL];

// ---------------- helpers ----------------
__device__ __forceinline__ uint32_t smem_u32(const void* p) {
    uint32_t a;
    asm("{ .reg .u64 t; cvta.to.shared.u64 t, %1; cvt.u32.u64 %0, t; }" : "=r"(a) : "l"(p));
    return a;
}
__device__ __forceinline__ void wsplit(float v, __nv_bfloat16* hp, __nv_bfloat16* lp, long i) {
    __nv_bfloat16 h = __float2bfloat16(v);
    hp[i] = h;
    lp[i] = __float2bfloat16(v - __bfloat162float(h));
}
__device__ __forceinline__ float sigf(float x) { return 1.0f / (1.0f + expf(-x)); }

__device__ __forceinline__ void mma_bf16(float* d, const uint32_t* a, const uint32_t* b) {
    asm volatile(
        "mma.sync.aligned.m16n8k16.row.col.f32.bf16.bf16.f32 "
        "{%0,%1,%2,%3}, {%4,%5,%6,%7}, {%8,%9}, {%0,%1,%2,%3};"
        : "+f"(d[0]), "+f"(d[1]), "+f"(d[2]), "+f"(d[3])
        : "r"(a[0]), "r"(a[1]), "r"(a[2]), "r"(a[3]), "r"(b[0]), "r"(b[1]));
}
__device__ __forceinline__ void ldsm4(uint32_t* r, uint32_t a) {
    asm volatile("ldmatrix.sync.aligned.m8n8.x4.shared.b16 {%0,%1,%2,%3}, [%4];"
        : "=r"(r[0]), "=r"(r[1]), "=r"(r[2]), "=r"(r[3]) : "r"(a));
}

// ================= split-bf16 tensor-core GEMM =================
// C[M,N] = (Ah+Al)[M,K] @ (Bh+Bl)[N,K]^T (+bias), fp32 accum.
// Block 128x128, 8 warps (2m x 4n), warp tile 64x32, K-chunk 32.
// 2-stage cp.async pipeline, ONE __syncthreads per chunk.
// __launch_bounds__(256, 2): cap regs at 128 so 2 CTAs/SM are guaranteed.
#define BM 128
#define BN 128
#define BK 32
#define PLANE (128 * 40)
#define PLANEB (PLANE * 2)
#define STAGEB (4 * PLANEB)
#define GEMM_SMEM (2 * STAGEB)      // 81920

__global__ void __launch_bounds__(256, 2) gemm_mma(
    long ah, long al, long bh, long bl,
    const float* __restrict__ bias_ext, int bias_mode,
    float* __restrict__ C_ext, long c_off, int N, int K)
{
    extern __shared__ __align__(16) __nv_bfloat16 dsm[];
    const __nv_bfloat16* Ah = g_bf + ah;
    const __nv_bfloat16* Al = g_bf + al;
    const __nv_bfloat16* Bh = g_bf + bh;
    const __nv_bfloat16* Bl = g_bf + bl;
    float* C = C_ext ? C_ext : (g_f + c_off);
    const float* bias = (bias_mode == 1) ? bias_ext : (bias_mode == 2 ? g_bio : nullptr);

    const int tid = threadIdx.x;
    const int warp = tid >> 5, lane = tid & 31;
    const int wm = warp & 1, wn = warp >> 1;
    const int g = lane >> 2, tig = lane & 3;

    const long bm = (long)blockIdx.x * BM;
    const int bn = blockIdx.y * BN;
    const int nsize = min(BN, N - bn);

    const int fr = tid >> 1;
    const int fc = (tid & 1) * 16;
    const long arow = bm + fr;
    const long brow = bn + (fr < nsize ? fr : 0);
    const int bok = (fr < nsize) ? 16 : 0;
    const uint32_t smb = smem_u32(dsm);
    const uint32_t doff = (uint32_t)(fr * 80 + fc * 2);

    const uint32_t laneA = (uint32_t)(((lane & 7) + (((lane >> 3) & 1) << 3)) * 80 + (lane >> 4) * 16);
    const uint32_t laneB = (uint32_t)(((lane & 7) + ((lane >> 4) << 3)) * 80 + ((lane >> 3) & 1) * 16);
    const uint32_t aBaseA = (uint32_t)(wm * 64 * 80) + laneA;
    const uint32_t aBaseB = (uint32_t)(wn * 32 * 80) + laneB;

    float acc[4][4][4];
#pragma unroll
    for (int i = 0; i < 4; i++)
#pragma unroll
        for (int j = 0; j < 4; j++)
#pragma unroll
            for (int v = 0; v < 4; v++) acc[i][j][v] = 0.f;

#define LOADCH(c_, st_) do {                                                           \
    const long k0_ = (long)(c_) * BK;                                                  \
    const uint32_t b_ = smb + (uint32_t)(st_) * STAGEB;                                \
    const __nv_bfloat16* pa_ = Ah + arow * K + k0_ + fc;                               \
    const __nv_bfloat16* qa_ = Al + arow * K + k0_ + fc;                               \
    const __nv_bfloat16* pb_ = Bh + brow * K + k0_ + fc;                               \
    const __nv_bfloat16* qb_ = Bl + brow * K + k0_ + fc;                               \
    asm volatile("cp.async.cg.shared.global [%0], [%1], 16;" :: "r"(b_ + doff), "l"(pa_)); \
    asm volatile("cp.async.cg.shared.global [%0], [%1], 16;" :: "r"(b_ + doff + 16), "l"(pa_ + 8)); \
    asm volatile("cp.async.cg.shared.global [%0], [%1], 16;" :: "r"(b_ + PLANEB + doff), "l"(qa_)); \
    asm volatile("cp.async.cg.shared.global [%0], [%1], 16;" :: "r"(b_ + PLANEB + doff + 16), "l"(qa_ + 8)); \
    asm volatile("cp.async.cg.shared.global [%0], [%1], 16, %2;" :: "r"(b_ + 2 * PLANEB + doff), "l"(pb_), "r"(bok)); \
    asm volatile("cp.async.cg.shared.global [%0], [%1], 16, %2;" :: "r"(b_ + 2 * PLANEB + doff + 16), "l"(pb_ + 8), "r"(bok)); \
    asm volatile("cp.async.cg.shared.global [%0], [%1], 16, %2;" :: "r"(b_ + 3 * PLANEB + doff), "l"(qb_), "r"(bok)); \
    asm volatile("cp.async.cg.shared.global [%0], [%1], 16, %2;" :: "r"(b_ + 3 * PLANEB + doff + 16), "l"(qb_ + 8), "r"(bok)); \
    asm volatile("cp.async.commit_group;");                                            \
} while (0)

    const int nch = K / BK;
    LOADCH(0, 0);
    for (int c = 0; c < nch; c++) {
        const int st = c & 1;
        asm volatile("cp.async.wait_group 0;");
        __syncthreads();
        // issue next chunk AFTER the barrier: all warps have finished reading
        // the stage being overwritten (last read at iter c-1). Copies overlap compute.
        if (c + 1 < nch) LOADCH(c + 1, st ^ 1);

        const uint32_t stb = smb + (uint32_t)st * STAGEB;
        const uint32_t pAh = stb + aBaseA;
        const uint32_t pAl = stb + PLANEB + aBaseA;
        const uint32_t pBh = stb + 2 * PLANEB + aBaseB;
        const uint32_t pBl = stb + 3 * PLANEB + aBaseB;

#pragma unroll
        for (int ks = 0; ks < 2; ks++) {
            const uint32_t ko = (uint32_t)(ks * 32);
            uint32_t ahf[4][4], alf[4][4], bhf[4][2], blf[4][2];
#pragma unroll
            for (int mf = 0; mf < 4; mf++) {
                ldsm4(ahf[mf], pAh + (uint32_t)(mf * 16 * 80) + ko);
                ldsm4(alf[mf], pAl + (uint32_t)(mf * 16 * 80) + ko);
            }
#pragma unroll
            for (int np = 0; np < 2; np++) {
                uint32_t bt[4];
                ldsm4(bt, pBh + (uint32_t)(np * 16 * 80) + ko);
                bhf[np * 2][0] = bt[0]; bhf[np * 2][1] = bt[1];
                bhf[np * 2 + 1][0] = bt[2]; bhf[np * 2 + 1][1] = bt[3];
                ldsm4(bt, pBl + (uint32_t)(np * 16 * 80) + ko);
                blf[np * 2][0] = bt[0]; blf[np * 2][1] = bt[1];
                blf[np * 2 + 1][0] = bt[2]; blf[np * 2 + 1][1] = bt[3];
            }
#pragma unroll
            for (int mf = 0; mf < 4; mf++)
#pragma unroll
                for (int nf = 0; nf < 4; nf++) {
                    mma_bf16(acc[mf][nf], ahf[mf], bhf[nf]);
                    mma_bf16(acc[mf][nf], ahf[mf], blf[nf]);
                    mma_bf16(acc[mf][nf], alf[mf], bhf[nf]);
                }
        }
    }

#pragma unroll
    for (int mf = 0; mf < 4; mf++) {
        const long row = bm + wm * 64 + mf * 16 + g;
#pragma unroll
        for (int nf = 0; nf < 4; nf++) {
            const int col = bn + wn * 32 + nf * 8 + tig * 2;
            if (col < N) {
                float bx = bias ? bias[col] : 0.f;
                float by = bias ? bias[col + 1] : 0.f;
                *(float2*)&C[row * N + col] =
                    make_float2(acc[mf][nf][0] + bx, acc[mf][nf][1] + by);
                *(float2*)&C[(row + 8) * N + col] =
                    make_float2(acc[mf][nf][2] + bx, acc[mf][nf][3] + by);
            }
        }
    }
#undef LOADCH
}

// ================= fused prep =================
// ranges: Wio 32768 | Uh 49152 | bio 640 | Wa 98304 | Wi 49152 | Wh 49152 |
//         W2 16384 | emb ED | inter RD | gather RD
#define PREP_TOTAL (32768L + 49152 + 640 + 98304 + 49152 + 49152 + 16384 + (long)ED + 2L * RD)
__global__ void __launch_bounds__(256) prep_all(
    const float* __restrict__ W_in, const float* __restrict__ b_in,
    const float* __restrict__ W_out, const float* __restrict__ b_out,
    const float* __restrict__ W_a, const float* __restrict__ U_h,
    const float* __restrict__ Wi, const float* __restrict__ Wh,
    const float* __restrict__ W2,
    const float* __restrict__ emb, const float* __restrict__ inter,
    const int* __restrict__ items)
{
    long i = (long)blockIdx.x * 256 + threadIdx.x;
    if (i < 32768) {                                    // Wio part of merged [640,128]
        int n = (int)(i >> 7), k = (int)(i & 127);
        float v = (n < 128) ? W_in[k * 128 + n] : W_out[k * 128 + (n - 128)];
        wsplit(v, g_bf + OW_WIOU, g_bf + OW_WIOU + 81920, i);
        return;
    }
    i -= 32768;
    if (i < 49152) {                                    // U_h part: rows 256..639
        int n = (int)(i >> 7), k = (int)(i & 127);
        wsplit(U_h[(long)k * 384 + n], g_bf + OW_WIOU + 32768, g_bf + OW_WIOU + 81920 + 32768, i);
        return;
    }
    i -= 49152;
    if (i < 640) {
        g_bio[i] = (i < 128) ? b_in[i] : (i < 256 ? b_out[i - 128] : 0.f);
        return;
    }
    i -= 640;
    if (i < 98304) {                                    // W_a [384,256]
        int n = (int)(i >> 8), k = (int)(i & 255);
        wsplit(W_a[(long)k * 384 + n], g_bf + OW_WA, g_bf + OW_WA + 98304, i);
        return;
    }
    i -= 98304;
    if (i < 49152) {                                    // Wi [384,128]
        int n = (int)(i >> 7), k = (int)(i & 127);
        wsplit(Wi[(long)k * 384 + n], g_bf + OW_WI, g_bf + OW_WI + 49152, i);
        return;
    }
    i -= 49152;
    if (i < 49152) {                                    // Wh [384,128]
        int n = (int)(i >> 7), k = (int)(i & 127);
        wsplit(Wh[(long)k * 384 + n], g_bf + OW_WH, g_bf + OW_WH + 49152, i);
        return;
    }
    i -= 49152;
    if (i < 16384) {                                    // W2 [128,128]
        int n = (int)(i >> 7), k = (int)(i & 127);
        wsplit(W2[(long)k * 128 + n], g_bf + OW_W2, g_bf + OW_W2 + 16384, i);
        return;
    }
    i -= 16384;
    if (i < (long)ED) {
        wsplit(emb[i], g_bf + BO_EBH, g_bf + BO_EBH + (long)ED, i);
        return;
    }
    i -= (long)ED;
    if (i < (long)RD) {
        wsplit(inter[i], g_bf + BO_IEH, g_bf + BO_IEH + (long)RD, i);
        return;
    }
    i -= (long)RD;
    if (i < (long)RD) {
        int row = (int)(i >> 7), d = (int)(i & 127);
        wsplit(emb[(long)items[row] * D + d], g_bf + BO_GAH, g_bf + BO_GAL, i);
    }
}

// ================= adjacency (hio from [ROWS,640] cols 0..255) =================
__global__ void __launch_bounds__(128) adj_kernel(const float* __restrict__ Ain, const float* __restrict__ Aout) {
    const float* hg = g_f + F_HG;
    const int b = blockIdx.x, d = threadIdx.x;
    __shared__ float sAi[L * L], sAo[L * L], shi[L * D], sho[L * D];
    const float* Aib = Ain + (long)b * L * L;
    const float* Aob = Aout + (long)b * L * L;
    for (int i = d; i < L * L; i += 128) { sAi[i] = Aib[i]; sAo[i] = Aob[i]; }
    for (int i = d; i < L * D; i += 128) {
        int m = i >> 7, dd = i & 127;
        long r = ((long)b * L + m) * 640;
        shi[i] = hg[r + dd];
        sho[i] = hg[r + 128 + dd];
    }
    __syncthreads();
    for (int l = 0; l < L; l++) {
        float si = 0.f, so = 0.f;
#pragma unroll 8
        for (int m = 0; m < L; m++) {
            si += sAi[l * L + m] * shi[m * D + d];
            so += sAo[l * L + m] * sho[m * D + d];
        }
        long o = ((long)b * L + l) * 256;
        wsplit(si, g_bf + BO_AH, g_bf + BO_AL, o + d);
        wsplit(so, g_bf + BO_AH, g_bf + BO_AL, o + 128 + d);
    }
}

// ================= GRU kernels =================
// GRU1: gi [ROWS,384] @ F_GI; gh = cols 256..639 of [ROWS,640] @ F_HG
__global__ void __launch_bounds__(256) gru1_kernel(const int* __restrict__ items, const float* __restrict__ emb) {
    long i = (long)blockIdx.x * 256 + threadIdx.x;
    if (i >= (long)RD) return;
    int row = (int)(i >> 7), d = (int)(i & 127);
    const float* gi = g_f + F_GI + (long)row * 384;
    const float* gh = g_f + F_HG + (long)row * 640 + 256;
    float r = sigf(gi[d] + gh[d]);
    float z = sigf(gi[128 + d] + gh[128 + d]);
    float n = tanhf(gi[256 + d] + r * gh[256 + d]);
    float hp = emb[(long)items[row] * D + d];
    wsplit((1.f - z) * n + z * hp, g_bf + BO_ITH, g_bf + BO_ITL, i);
}

// GRU2: gi [ROWS,384] @ F_GI; gh [ROWS,384] @ F_HG
__global__ void __launch_bounds__(256) gru2_kernel(const float* __restrict__ inter) {
    long i = (long)blockIdx.x * 256 + threadIdx.x;
    if (i >= (long)RD) return;
    int row = (int)(i >> 7), d = (int)(i & 127);
    const float* gi = g_f + F_GI + (long)row * 384;
    const float* gh = g_f + F_HG + (long)row * 384;
    float r = sigf(gi[d] + gh[d]);
    float z = sigf(gi[128 + d] + gh[128 + d]);
    float n = tanhf(gi[256 + d] + r * gh[256 + d]);
    float v = (1.f - z) * n + z * inter[i];
    g_f[F_FIN + i] = v;
    wsplit(v, g_bf + BO_FNH, g_bf + BO_FNL, i);
}

// ================= attention readout =================
__global__ void __launch_bounds__(128) readout_kernel(
    const int* __restrict__ seq_len,
    const float* __restrict__ W1, const float* __restrict__ b1,
    const float* __restrict__ wq, const float* __restrict__ bq,
    const float* __restrict__ W3, const float* __restrict__ b3)
{
    const float* fin = g_f + F_FIN;
    const float* fW2 = g_f + F_FW2;
    const int b = blockIdx.x, d = threadIdx.x;
    __shared__ float svn[D], sg_sh[D], gmat[L * D], alpha[L];

    const int sl = seq_len[b];
    const float* finb = fin + (long)b * L * D;
    svn[d] = finb[(long)(sl - 1) * D + d];
    __syncthreads();

    float q = b1[d];
    for (int k = 0; k < D; k++) q += svn[k] * W1[k * D + d];

    const float* fW2b = fW2 + (long)b * L * D;
    for (int l = 0; l < L; l++)
        gmat[l * D + d] = sigf(q + fW2b[l * D + d]);
    __syncthreads();

    int w = d >> 5, lane = d & 31;
    for (int l = w; l < L; l += 4) {
        float p = 0.f;
        for (int kk = lane; kk < D; kk += 32) p += gmat[l * D + kk] * wq[kk];
#pragma unroll
        for (int off = 16; off; off >>= 1) p += __shfl_xor_sync(0xFFFFFFFFu, p, off);
        if (lane == 0) alpha[l] = p + bq[0];
    }
    __syncthreads();

    float sg = 0.f;
    for (int l = 0; l < sl; l++) sg += alpha[l] * finb[(long)l * D + d];
    sg_sh[d] = sg;
    __syncthreads();

    float o = b3[d];
    for (int k = 0; k < D; k++) {
        o += svn[k]   * W3[k * D + d];
        o += sg_sh[k] * W3[(D + k) * D + d];
    }
    wsplit(o, g_bf + BO_HSH, g_bf + BO_HSL, (long)b * D + d);
}

// ================= launcher =================
extern "C" void kernel_launch(void* const* d_in, const int* in_sizes, int n_in,
                              void* d_out, int out_size)
{
    const int*   items  = (const int*)d_in[0];
    const float* A_in   = (const float*)d_in[1];
    const float* A_out  = (const float*)d_in[2];
    const float* inter  = (const float*)d_in[3];
    const int*   seqlen = (const int*)d_in[4];
    const float* emb    = (const float*)d_in[5];
    const float* W_in   = (const float*)d_in[6];
    const float* b_in   = (const float*)d_in[7];
    const float* W_out  = (const float*)d_in[8];
    const float* b_out  = (const float*)d_in[9];
    const float* W_a    = (const float*)d_in[10];
    const float* U_h    = (const float*)d_in[11];
    const float* b_gru  = (const float*)d_in[12];
    const float* Wi     = (const float*)d_in[13];
    const float* bi     = (const float*)d_in[14];
    const float* Wh     = (const float*)d_in[15];
    const float* bh     = (const float*)d_in[16];
    const float* W1     = (const float*)d_in[17];
    const float* b1     = (const float*)d_in[18];
    const float* W2     = (const float*)d_in[19];
    const float* b2     = (const float*)d_in[20];
    const float* wq     = (const float*)d_in[21];
    const float* bq     = (const float*)d_in[22];
    const float* W3     = (const float*)d_in[23];
    const float* b3     = (const float*)d_in[24];
    float* scores = (float*)d_out;

    cudaFuncSetAttribute(gemm_mma, cudaFuncAttributeMaxDynamicSharedMemorySize, GEMM_SMEM);

    const int MT = ROWS / 128;   // 256 M-tiles

    prep_all<<<(int)((PREP_TOTAL + 255) / 256), 256>>>(W_in, b_in, W_out, b_out, W_a, U_h,
                                                       Wi, Wh, W2, emb, inter, items);
    // [hio | gh] = gathered @ [W_in|W_out|U_h] + [bio|0]   (N=640, K=128)
    gemm_mma<<<dim3(MT, 5), 256, GEMM_SMEM>>>(BO_GAH, BO_GAL, OW_WIOU, OW_WIOU + 81920,
                                              nullptr, 2, nullptr, F_HG, 640, 128);
    adj_kernel<<<BATCH, 128>>>(A_in, A_out);
    gemm_mma<<<dim3(MT, 3), 256, GEMM_SMEM>>>(BO_AH, BO_AL, OW_WA, OW_WA + 98304,
                                              b_gru, 1, nullptr, F_GI, 384, 256);
    gru1_kernel<<<(RD + 255) / 256, 256>>>(items, emb);
    gemm_mma<<<dim3(MT, 3), 256, GEMM_SMEM>>>(BO_ITH, BO_ITL, OW_WI, OW_WI + 49152,
                                              bi, 1, nullptr, F_GI, 384, 128);
    gemm_mma<<<dim3(MT, 3), 256, GEMM_SMEM>>>(BO_IEH, BO_IEL, OW_WH, OW_WH + 49152,
                                              bh, 1, nullptr, F_HG, 384, 128);
    gru2_kernel<<<(RD + 255) / 256, 256>>>(inter);
    gemm_mma<<<dim3(MT, 1), 256, GEMM_SMEM>>>(BO_FNH, BO_FNL, OW_W2, OW_W2 + 16384,
                                              b2, 1, nullptr, F_FW2, 128, 128);
    readout_kernel<<<BATCH, 128>>>(seqlen, W1, b1, wq, bq, W3, b3);
    gemm_mma<<<dim3(BATCH / 128, (NNODE + 127) / 128), 256, GEMM_SMEM>>>(
        BO_HSH, BO_HSL, BO_EBH, BO_EBL, nullptr, 0, scores, 0, NNODE, 128);
}